// round 1
// baseline (speedup 1.0000x reference)
#include <cuda_runtime.h>
#include <cstdint>

#define BB 8
#define LL 2048
#define VV 8192
#define CC 64
#define FF 130

// scratch: [B*L][132]  (cols 0..64 = left feats+dens, 65..129 = right feats+dens)
static __device__ float g_x[BB * LL * 132];

// ---------- packed f32x2 helpers ----------
__device__ __forceinline__ unsigned long long fma2(unsigned long long a,
                                                   unsigned long long b,
                                                   unsigned long long c) {
    unsigned long long d;
    asm("fma.rn.f32x2 %0, %1, %2, %3;" : "=l"(d) : "l"(a), "l"(b), "l"(c));
    return d;
}
__device__ __forceinline__ unsigned long long pack2(float x, float y) {
    unsigned long long d;
    asm("mov.b64 %0, {%1, %2};" : "=l"(d) : "f"(x), "f"(y));
    return d;
}
__device__ __forceinline__ void unpack2(unsigned long long v, float& x, float& y) {
    asm("mov.b64 {%0, %1}, %2;" : "=f"(x), "=f"(y) : "l"(v));
}
__device__ __forceinline__ void cp16(uint32_t dst, const void* src) {
    asm volatile("cp.async.cg.shared.global [%0], [%1], 16;" :: "r"(dst), "l"(src));
}

// ---------- fused RBF interpolation ----------
// grid: (LL/TL, 2 sides, BB); block: 32 threads, 1 query row per thread
#define TL 32
#define TV 32
#define NCH (VV / TV)

__global__ void __launch_bounds__(32) interp_kernel(
    const float* __restrict__ locsL, const float* __restrict__ locsR,
    const float* __restrict__ vertsL, const float* __restrict__ vertsR,
    const float* __restrict__ featsL, const float* __restrict__ featsR,
    float* __restrict__ xout) {
    __shared__ __align__(16) float fs[2][TV * CC];     // 2 x 8KB feats chunks
    __shared__ __align__(16) float vs_s[2][TV * 3];    // verts chunks

    const int tid  = threadIdx.x;
    const int lt   = blockIdx.x;
    const int side = blockIdx.y;
    const int b    = blockIdx.z;

    const float* locs  = side ? locsR : locsL;
    const float* verts = side ? vertsR : vertsL;
    const float* feats = side ? featsR : featsL;

    const int l = lt * TL + tid;
    const float* lp = locs + ((size_t)b * LL + l) * 3;
    const float px = lp[0], py = lp[1], pz = lp[2];
    const float n2 = px * px + py * py + pz * pz;

    const float* fbase = feats + (size_t)b * VV * CC;
    const float* vbase = verts + (size_t)b * VV * 3;

    const uint32_t fs_addr = (uint32_t)__cvta_generic_to_shared(&fs[0][0]);
    const uint32_t vs_addr = (uint32_t)__cvta_generic_to_shared(&vs_s[0][0]);

    unsigned long long acc[32];
#pragma unroll
    for (int i = 0; i < 32; i++) acc[i] = 0ull;
    float dens = 0.f;

#define STAGE(bufi, chunk)                                                     \
    do {                                                                       \
        const float* fsrc = fbase + (size_t)(chunk) * (TV * CC);               \
        const uint32_t fd = fs_addr + (bufi) * (TV * CC * 4);                  \
        _Pragma("unroll")                                                      \
        for (int i_ = 0; i_ < 16; i_++)                                        \
            cp16(fd + (tid + i_ * 32) * 16, fsrc + (tid + i_ * 32) * 4);       \
        const float* vsrc = vbase + (size_t)(chunk) * (TV * 3);                \
        if (tid < 24)                                                          \
            cp16(vs_addr + (bufi) * (TV * 3 * 4) + tid * 16, vsrc + tid * 4);  \
        asm volatile("cp.async.commit_group;");                                \
    } while (0)

    STAGE(0, 0);

    for (int k = 0; k < NCH; k++) {
        const int buf = k & 1;
        if (k + 1 < NCH) {
            STAGE(buf ^ 1, k + 1);
            asm volatile("cp.async.wait_group 1;");
        } else {
            asm volatile("cp.async.wait_group 0;");
        }
        __syncthreads();

        const float* vsp = &vs_s[buf][0];
        const float* fsp = &fs[buf][0];
#pragma unroll 2
        for (int j = 0; j < TV; j++) {
            const float vx = vsp[3 * j + 0];
            const float vy = vsp[3 * j + 1];
            const float vz = vsp[3 * j + 2];
            const float t  = fmaf(px, vx, fmaf(py, vy, pz * vz));
            const float n1 = fmaf(vx, vx, fmaf(vy, vy, vz * vz));
            const float d2 = fmaf(-2.f, t, n2 + n1);
            const float d  = sqrtf(fmaxf(d2, 0.f));
            const float w  = __expf(d * -0.4f);   // exp(-d/2.5)
            dens += w;
            const unsigned long long wp = pack2(w, w);
            const ulonglong2* fr = (const ulonglong2*)(fsp + j * CC);
#pragma unroll
            for (int i = 0; i < 16; i++) {
                ulonglong2 q = fr[i];
                acc[2 * i + 0] = fma2(wp, q.x, acc[2 * i + 0]);
                acc[2 * i + 1] = fma2(wp, q.y, acc[2 * i + 1]);
            }
        }
        __syncthreads();
    }
#undef STAGE

    const float inv = 1.f / dens;
    float* orow = xout + ((size_t)(b * LL + l)) * 132 + side * 65;
#pragma unroll
    for (int i = 0; i < 32; i++) {
        float a, c;
        unpack2(acc[i], a, c);
        orow[2 * i + 0] = a * inv;
        orow[2 * i + 1] = c * inv;
    }
    orow[64] = dens;
}

// ---------- tiny MLP: out = (relu(x@w1^T + b1)) @ w2^T + b2 ----------
// one warp per row; grid = B*L/8 blocks of 256 threads
__global__ void __launch_bounds__(256) mlp_kernel(
    const float* __restrict__ x,
    const float* __restrict__ w1, const float* __restrict__ b1,
    const float* __restrict__ w2, const float* __restrict__ b2,
    float* __restrict__ out) {
    __shared__ float xs[8][132];
    const int warp = threadIdx.x >> 5;
    const int lane = threadIdx.x & 31;
    const int row  = blockIdx.x * 8 + warp;

    const float* xr = x + (size_t)row * 132;
    for (int i = lane; i < FF; i += 32) xs[warp][i] = xr[i];
    __syncwarp();

    float oacc = 0.f;
    for (int j = lane; j < FF; j += 32) {
        const float2* wr = (const float2*)(w1 + (size_t)j * FF);
        float h0 = b1[j], h1 = 0.f;
#pragma unroll 13
        for (int kk = 0; kk < FF / 2; kk++) {
            const float2 ww = wr[kk];
            h0 = fmaf(xs[warp][2 * kk + 0], ww.x, h0);
            h1 = fmaf(xs[warp][2 * kk + 1], ww.y, h1);
        }
        float h = fmaxf(h0 + h1, 0.f);
        oacc = fmaf(h, w2[j], oacc);
    }
#pragma unroll
    for (int o = 16; o > 0; o >>= 1)
        oacc += __shfl_xor_sync(0xFFFFFFFFu, oacc, o);
    if (lane == 0) out[row] = oacc + b2[0];
}

extern "C" void kernel_launch(void* const* d_in, const int* in_sizes, int n_in,
                              void* d_out, int out_size) {
    (void)in_sizes; (void)n_in; (void)out_size;
    const float* locsL  = (const float*)d_in[0];
    const float* locsR  = (const float*)d_in[1];
    const float* vertsL = (const float*)d_in[2];
    const float* vertsR = (const float*)d_in[3];
    const float* featsL = (const float*)d_in[4];
    const float* featsR = (const float*)d_in[5];
    const float* w1     = (const float*)d_in[6];
    const float* b1     = (const float*)d_in[7];
    const float* w2     = (const float*)d_in[8];
    const float* b2     = (const float*)d_in[9];
    float* out = (float*)d_out;

    float* xptr = nullptr;
    cudaGetSymbolAddress((void**)&xptr, g_x);

    dim3 grid(LL / TL, 2, BB);
    interp_kernel<<<grid, 32>>>(locsL, locsR, vertsL, vertsR, featsL, featsR, xptr);
    mlp_kernel<<<(BB * LL) / 8, 256>>>(xptr, w1, b1, w2, b2, out);
}

// round 2
// speedup vs baseline: 1.1440x; 1.1440x over previous
#include <cuda_runtime.h>
#include <cstdint>

#define BB   8
#define LL   2048
#define VV   8192
#define CC   64
#define SS   4              // V-split factor
#define VSUB (VV / SS)      // 2048 verts per CTA
#define TVC  64             // verts per smem chunk
#define NCHK (VSUB / TVC)   // 32 chunks
#define ROWF 132            // scratch row stride (floats)
#define NQ   (BB * LL)      // 16384 output rows

// [SS][B*L][132]: cols 0..63 fL-sum, 64..127 fR-sum, 128 densL, 129 densR
static __device__ float  g_part[SS * NQ * ROWF];
static __device__ float4 g_vn[2 * BB * VV];     // (x,y,z,|v|^2) per (b,side,v)
static __device__ float  g_w1t[132 * 132];      // w1 transposed+padded: w1t[k][j]
static __device__ float  g_b1p[132];
static __device__ float  g_w2p[132];

// ---------- packed f32x2 helpers ----------
__device__ __forceinline__ unsigned long long fma2(unsigned long long a,
                                                   unsigned long long b,
                                                   unsigned long long c) {
    unsigned long long d;
    asm("fma.rn.f32x2 %0, %1, %2, %3;" : "=l"(d) : "l"(a), "l"(b), "l"(c));
    return d;
}
__device__ __forceinline__ unsigned long long pack2(float x, float y) {
    unsigned long long d;
    asm("mov.b64 %0, {%1, %2};" : "=l"(d) : "f"(x), "f"(y));
    return d;
}
__device__ __forceinline__ void cp16(uint32_t dst, const void* src) {
    asm volatile("cp.async.cg.shared.global [%0], [%1], 16;" :: "r"(dst), "l"(src));
}

// ---------- prep 1: verts + |v|^2 as float4 ----------
__global__ void prep_vn_kernel(const float* __restrict__ vertsL,
                               const float* __restrict__ vertsR) {
    const int v  = blockIdx.x * 256 + threadIdx.x;
    const int bs = blockIdx.y;
    const int b = bs >> 1, side = bs & 1;
    const float* vp = (side ? vertsR : vertsL) + ((size_t)b * VV + v) * 3;
    const float x = vp[0], y = vp[1], z = vp[2];
    g_vn[(size_t)bs * VV + v] = make_float4(x, y, z, fmaf(x, x, fmaf(y, y, z * z)));
}

// ---------- prep 2: transpose/pad MLP weights ----------
__global__ void prep_w1_kernel(const float* __restrict__ w1,
                               const float* __restrict__ b1,
                               const float* __restrict__ w2) {
    const int idx = blockIdx.x * 256 + threadIdx.x;
    if (idx < 132 * 132) {
        const int k = idx / 132, j = idx % 132;
        g_w1t[idx] = (j < 130 && k < 130) ? w1[j * 130 + k] : 0.f;
    }
    if (blockIdx.x == 0 && idx < 132) {
        g_b1p[idx] = (idx < 130) ? b1[idx] : 0.f;
        g_w2p[idx] = (idx < 130) ? w2[idx] : 0.f;
    }
}

// ---------- fused RBF interpolation (partial sums) ----------
// grid: (L/128, SS, 2*B); block: 128 threads (4 warps share the verts tile)
__global__ void __launch_bounds__(128, 4) interp_kernel(
    const float* __restrict__ locsL, const float* __restrict__ locsR,
    const float* __restrict__ featsL, const float* __restrict__ featsR) {
    __shared__ __align__(16) float  fs[2][TVC * CC];   // 2 x 16 KB
    __shared__ __align__(16) float4 vs[2][TVC];        // 2 x 1 KB

    const int tid  = threadIdx.x;
    const int lt   = blockIdx.x;
    const int s    = blockIdx.y;
    const int bs   = blockIdx.z;
    const int b = bs >> 1, side = bs & 1;

    const int l = lt * 128 + tid;
    const float* lp = (side ? locsR : locsL) + ((size_t)b * LL + l) * 3;
    const float px = lp[0], py = lp[1], pz = lp[2];
    const float n2 = fmaf(px, px, fmaf(py, py, pz * pz));

    const float*  fbase = (side ? featsR : featsL) + ((size_t)b * VV + s * VSUB) * CC;
    const float4* vbase = g_vn + (size_t)bs * VV + s * VSUB;

    const uint32_t fs_addr = (uint32_t)__cvta_generic_to_shared(&fs[0][0]);
    const uint32_t vs_addr = (uint32_t)__cvta_generic_to_shared(&vs[0][0]);

    unsigned long long acc[32];
#pragma unroll
    for (int i = 0; i < 32; i++) acc[i] = 0ull;
    float dens = 0.f;

#define STAGE(bufi, chunk)                                                      \
    do {                                                                        \
        const float* srcF = fbase + (size_t)(chunk) * (TVC * CC);               \
        const uint32_t fd = fs_addr + (bufi) * (TVC * CC * 4);                  \
        _Pragma("unroll")                                                       \
        for (int i_ = 0; i_ < (TVC * CC / 4 / 128); i_++)                       \
            cp16(fd + (tid + i_ * 128) * 16, srcF + (tid + i_ * 128) * 4);      \
        if (tid < TVC)                                                          \
            cp16(vs_addr + (bufi) * (TVC * 16) + tid * 16,                      \
                 vbase + (size_t)(chunk) * TVC + tid);                          \
        asm volatile("cp.async.commit_group;");                                 \
    } while (0)

    STAGE(0, 0);

    for (int c = 0; c < NCHK; c++) {
        const int buf = c & 1;
        if (c + 1 < NCHK) {
            STAGE(buf ^ 1, c + 1);
            asm volatile("cp.async.wait_group 1;");
        } else {
            asm volatile("cp.async.wait_group 0;");
        }
        __syncthreads();

        const float4* vsp = &vs[buf][0];
        const float*  fsp = &fs[buf][0];
#pragma unroll 2
        for (int j = 0; j < TVC; j++) {
            const float4 vv = vsp[j];
            const float t  = fmaf(px, vv.x, fmaf(py, vv.y, pz * vv.z));
            const float d2 = fmaf(-2.f, t, n2 + vv.w);
            const float d  = sqrtf(fmaxf(d2, 0.f));
            const float w  = __expf(d * -0.4f);      // exp(-d/2.5)
            dens += w;
            const unsigned long long wp = pack2(w, w);
            const ulonglong2* fr = (const ulonglong2*)(fsp + j * CC);
#pragma unroll
            for (int i = 0; i < 8; i++) {
                ulonglong2 q = fr[i];
                acc[2 * i + 0] = fma2(wp, q.x, acc[2 * i + 0]);
                acc[2 * i + 1] = fma2(wp, q.y, acc[2 * i + 1]);
            }
#pragma unroll
            for (int i = 8; i < 16; i++) {
                ulonglong2 q = fr[i];
                acc[2 * i + 0] = fma2(wp, q.x, acc[2 * i + 0]);
                acc[2 * i + 1] = fma2(wp, q.y, acc[2 * i + 1]);
            }
        }
        __syncthreads();
    }
#undef STAGE

    // unnormalized partial sums + dens
    const size_t row = (size_t)s * NQ + (size_t)b * LL + l;
    float* orow = g_part + row * ROWF + side * 64;
    ulonglong2* ov = (ulonglong2*)orow;
#pragma unroll
    for (int i = 0; i < 16; i++) {
        ulonglong2 q; q.x = acc[2 * i]; q.y = acc[2 * i + 1];
        ov[i] = q;
    }
    g_part[row * ROWF + 128 + side] = dens;
}

// ---------- MLP: sum partials, normalize, 130->130 relu ->1 ----------
// block 256 = 8 warps, each warp handles 2 query rows
__global__ void __launch_bounds__(256) mlp_kernel(
    const float* __restrict__ b2, float* __restrict__ out) {
    __shared__ float xs[8][2][132];
    const int warp = threadIdx.x >> 5;
    const int lane = threadIdx.x & 31;
    const int q0 = (blockIdx.x * 8 + warp) * 2;

#pragma unroll
    for (int qq = 0; qq < 2; qq++) {
        const int q = q0 + qq;
        float v[5];
#pragma unroll
        for (int m = 0; m < 5; m++) {
            const int c = lane + 32 * m;
            float sum = 0.f;
            if (c < 130) {
#pragma unroll
                for (int s = 0; s < SS; s++)
                    sum += g_part[((size_t)s * NQ + q) * ROWF + c];
            }
            v[m] = sum;
        }
        const float dl = __shfl_sync(0xFFFFFFFFu, v[4], 0);
        const float dr = __shfl_sync(0xFFFFFFFFu, v[4], 1);
        const float il = 1.f / dl, ir = 1.f / dr;
#pragma unroll
        for (int m = 0; m < 5; m++) {
            const int c = lane + 32 * m;
            if (c < 64)        xs[warp][qq][c] = v[m] * il;
            else if (c < 128)  xs[warp][qq][c + 1] = v[m] * ir;
            else if (c == 128) xs[warp][qq][64] = dl;
            else if (c == 129) xs[warp][qq][129] = dr;
        }
    }
    __syncwarp();

    const float4* wv = (const float4*)g_w1t;   // 33 float4 per k-row
    float4 hA0 = make_float4(0, 0, 0, 0), hA1 = hA0, hB0 = hA0, hB1 = hA0;
#pragma unroll 2
    for (int k = 0; k < 130; k++) {
        const float4 wA = wv[k * 33 + lane];
        const float4 wB = wv[k * 33 + 32];
        const float x0 = xs[warp][0][k];
        const float x1 = xs[warp][1][k];
        hA0.x = fmaf(wA.x, x0, hA0.x); hA0.y = fmaf(wA.y, x0, hA0.y);
        hA0.z = fmaf(wA.z, x0, hA0.z); hA0.w = fmaf(wA.w, x0, hA0.w);
        hA1.x = fmaf(wA.x, x1, hA1.x); hA1.y = fmaf(wA.y, x1, hA1.y);
        hA1.z = fmaf(wA.z, x1, hA1.z); hA1.w = fmaf(wA.w, x1, hA1.w);
        hB0.x = fmaf(wB.x, x0, hB0.x); hB0.y = fmaf(wB.y, x0, hB0.y);
        hB0.z = fmaf(wB.z, x0, hB0.z); hB0.w = fmaf(wB.w, x0, hB0.w);
        hB1.x = fmaf(wB.x, x1, hB1.x); hB1.y = fmaf(wB.y, x1, hB1.y);
        hB1.z = fmaf(wB.z, x1, hB1.z); hB1.w = fmaf(wB.w, x1, hB1.w);
    }

    const float4 b1A = ((const float4*)g_b1p)[lane];
    const float4 w2A = ((const float4*)g_w2p)[lane];
    const float4 b1B = ((const float4*)g_b1p)[32];
    const float4 w2B = ((const float4*)g_w2p)[32];

    float r0 = fmaxf(hA0.x + b1A.x, 0.f) * w2A.x + fmaxf(hA0.y + b1A.y, 0.f) * w2A.y
             + fmaxf(hA0.z + b1A.z, 0.f) * w2A.z + fmaxf(hA0.w + b1A.w, 0.f) * w2A.w;
    float r1 = fmaxf(hA1.x + b1A.x, 0.f) * w2A.x + fmaxf(hA1.y + b1A.y, 0.f) * w2A.y
             + fmaxf(hA1.z + b1A.z, 0.f) * w2A.z + fmaxf(hA1.w + b1A.w, 0.f) * w2A.w;
    if (lane == 0) {
        r0 += fmaxf(hB0.x + b1B.x, 0.f) * w2B.x + fmaxf(hB0.y + b1B.y, 0.f) * w2B.y
            + fmaxf(hB0.z + b1B.z, 0.f) * w2B.z + fmaxf(hB0.w + b1B.w, 0.f) * w2B.w;
        r1 += fmaxf(hB1.x + b1B.x, 0.f) * w2B.x + fmaxf(hB1.y + b1B.y, 0.f) * w2B.y
            + fmaxf(hB1.z + b1B.z, 0.f) * w2B.z + fmaxf(hB1.w + b1B.w, 0.f) * w2B.w;
    }
#pragma unroll
    for (int o = 16; o > 0; o >>= 1) {
        r0 += __shfl_xor_sync(0xFFFFFFFFu, r0, o);
        r1 += __shfl_xor_sync(0xFFFFFFFFu, r1, o);
    }
    if (lane == 0) {
        const float bb = b2[0];
        out[q0 + 0] = r0 + bb;
        out[q0 + 1] = r1 + bb;
    }
}

extern "C" void kernel_launch(void* const* d_in, const int* in_sizes, int n_in,
                              void* d_out, int out_size) {
    (void)in_sizes; (void)n_in; (void)out_size;
    const float* locsL  = (const float*)d_in[0];
    const float* locsR  = (const float*)d_in[1];
    const float* vertsL = (const float*)d_in[2];
    const float* vertsR = (const float*)d_in[3];
    const float* featsL = (const float*)d_in[4];
    const float* featsR = (const float*)d_in[5];
    const float* w1     = (const float*)d_in[6];
    const float* b1     = (const float*)d_in[7];
    const float* w2     = (const float*)d_in[8];
    const float* b2     = (const float*)d_in[9];
    float* out = (float*)d_out;

    prep_vn_kernel<<<dim3(VV / 256, 16), 256>>>(vertsL, vertsR);
    prep_w1_kernel<<<69, 256>>>(w1, b1, w2);
    interp_kernel<<<dim3(LL / 128, SS, 2 * BB), 128>>>(locsL, locsR, featsL, featsR);
    mlp_kernel<<<NQ / 16, 256>>>(b2, out);
}